// round 12
// baseline (speedup 1.0000x reference)
#include <cuda_runtime.h>
#include <cuda_bf16.h>
#include <cstdint>

// Problem constants (fixed by the dataset)
#define NN   50000
#define EE   800000
#define NFK  256
#define HD   128
#define NL   3

typedef unsigned long long ull;

// Scratch: static device arrays (no runtime allocation allowed)
__device__ __align__(16) __nv_bfloat16 g_nf16[NN * NFK];  // bf16 node_feat (25.6 MB)
__device__ __align__(16) __nv_bfloat16 g_agg[NN * HD];    // bf16 GEMM input
__device__ __align__(16) __nv_bfloat16 g_h0[NN * HD];     // bf16 h ping
__device__ __align__(16) __nv_bfloat16 g_h1[NN * HD];     // bf16 h pong
__device__ __align__(16) __nv_bfloat16 g_wtnh[128 * NFK]; // Wn^T hi
__device__ __align__(16) __nv_bfloat16 g_wtnl[128 * NFK]; // Wn^T lo
__device__ __align__(16) __nv_bfloat16 g_wtgh[128 * HD];  // Wgcn^T hi
__device__ __align__(16) __nv_bfloat16 g_wtgl[128 * HD];  // Wgcn^T lo
__device__ float g_colsum[(NL + 1) * HD];                 // 512 floats
// CSR scratch
__device__ int   g_cnt[NN];
__device__ int   g_rowptr[NN + 1];
__device__ int   g_offs[NN];
__device__ int   g_esrc[EE];
__device__ float g_rscale[EE];

// ---------------------------------------------------------------------------
// low-level helpers
// ---------------------------------------------------------------------------
__device__ __forceinline__ uint32_t smem_u32(const void* p) {
    uint32_t a;
    asm("{ .reg .u64 tmp; cvta.to.shared.u64 tmp, %1; cvt.u32.u64 %0, tmp; }"
        : "=r"(a) : "l"(p));
    return a;
}
__device__ __forceinline__ void cp16(uint32_t smem_addr, const void* g)
{
    asm volatile("cp.async.cg.shared.global [%0], [%1], 16;" :: "r"(smem_addr), "l"(g));
}
__device__ __forceinline__ void cp_commit() { asm volatile("cp.async.commit_group;"); }
__device__ __forceinline__ void cp_wait0()  { asm volatile("cp.async.wait_group 0;" ::: "memory"); }

__device__ __forceinline__ void ldsm4(unsigned* r, uint32_t addr) {
    asm volatile("ldmatrix.sync.aligned.m8n8.x4.shared.b16 {%0,%1,%2,%3}, [%4];"
        : "=r"(r[0]), "=r"(r[1]), "=r"(r[2]), "=r"(r[3]) : "r"(addr));
}
__device__ __forceinline__ void mma16816(float* c, const unsigned* a, const unsigned* b) {
    asm volatile("mma.sync.aligned.m16n8k16.row.col.f32.bf16.bf16.f32 "
        "{%0,%1,%2,%3}, {%4,%5,%6,%7}, {%8,%9}, {%0,%1,%2,%3};"
        : "+f"(c[0]), "+f"(c[1]), "+f"(c[2]), "+f"(c[3])
        : "r"(a[0]), "r"(a[1]), "r"(a[2]), "r"(a[3]), "r"(b[0]), "r"(b[1]));
}

// ---------------------------------------------------------------------------
// Prep kernels (tiny, once per replay)
// ---------------------------------------------------------------------------
// fp32 -> bf16 block convert (8 elems / thread)
__global__ void cvt_kernel(const float* __restrict__ in, __nv_bfloat16* __restrict__ out,
                           int total8)
{
    int i = blockIdx.x * blockDim.x + threadIdx.x;
    if (i >= total8) return;
    const float4* p = reinterpret_cast<const float4*>(in) + i * 2;
    float4 v0 = p[0], v1 = p[1];
    __nv_bfloat162 b0 = __floats2bfloat162_rn(v0.x, v0.y);
    __nv_bfloat162 b1 = __floats2bfloat162_rn(v0.z, v0.w);
    __nv_bfloat162 b2 = __floats2bfloat162_rn(v1.x, v1.y);
    __nv_bfloat162 b3 = __floats2bfloat162_rn(v1.z, v1.w);
    uint4 u = make_uint4(*reinterpret_cast<unsigned*>(&b0), *reinterpret_cast<unsigned*>(&b1),
                         *reinterpret_cast<unsigned*>(&b2), *reinterpret_cast<unsigned*>(&b3));
    reinterpret_cast<uint4*>(out)[i] = u;
}

// W[k][n] fp32 -> Wt_hi[n][k], Wt_lo[n][k] bf16 (hi/lo split)
__global__ void prepw_kernel(const float* __restrict__ W,
                             __nv_bfloat16* __restrict__ WtH,
                             __nv_bfloat16* __restrict__ WtL, int K)
{
    int i = blockIdx.x * blockDim.x + threadIdx.x;
    if (i >= 128 * K) return;
    int n = i / K, k = i - n * K;
    float v = W[k * 128 + n];
    __nv_bfloat16 h = __float2bfloat16_rn(v);
    WtH[i] = h;
    WtL[i] = __float2bfloat16_rn(v - __bfloat162float(h));
}

// ---------------------------------------------------------------------------
// CSR build (per replay; order within a dst bucket is arbitrary)
// ---------------------------------------------------------------------------
__global__ void hist_kernel(const int* __restrict__ dst, int e)
{
    int i = blockIdx.x * blockDim.x + threadIdx.x;
    if (i < e) atomicAdd(&g_cnt[dst[i]], 1);
}

__global__ __launch_bounds__(1024)
void scan_kernel(int n)
{
    __shared__ int part[1024];
    int t = threadIdx.x;
    int chunk = (n + 1023) >> 10;
    int beg = t * chunk, end = min(beg + chunk, n);
    int s = 0;
    for (int i = beg; i < end; i++) s += g_cnt[i];
    part[t] = s;
    __syncthreads();
    for (int off = 1; off < 1024; off <<= 1) {
        int v = (t >= off) ? part[t - off] : 0;
        __syncthreads();
        part[t] += v;
        __syncthreads();
    }
    int run = part[t] - s;
    for (int i = beg; i < end; i++) {
        g_rowptr[i] = run;
        g_offs[i]   = run;
        run += g_cnt[i];
    }
    if (end == n) g_rowptr[n] = run;
}

__global__ void fill_kernel(const int* __restrict__ src, const int* __restrict__ dst,
                            const float* __restrict__ degree, int e)
{
    int i = blockIdx.x * blockDim.x + threadIdx.x;
    if (i >= e) return;
    int s = src[i], d = dst[i];
    int pos = atomicAdd(&g_offs[d], 1);
    g_esrc[pos]   = s;
    g_rscale[pos] = 1.0f / degree[s];
}

// ---------------------------------------------------------------------------
// Gather over bf16 hidden states, fp32 accumulation, bf16 output.
// MODE 0: out[v] = sum_{u->v} h[u]
// MODE 1: out[v] = h[v] + sum_{u->v} h[u] * (1/deg[u])
// ---------------------------------------------------------------------------
__device__ __forceinline__ void acc_bf(float4& acc, ull x, float c)
{
    const __nv_bfloat162* p = reinterpret_cast<const __nv_bfloat162*>(&x);
    float2 f0 = __bfloat1622float2(p[0]);
    float2 f1 = __bfloat1622float2(p[1]);
    acc.x = fmaf(f0.x, c, acc.x); acc.y = fmaf(f0.y, c, acc.y);
    acc.z = fmaf(f1.x, c, acc.z); acc.w = fmaf(f1.y, c, acc.w);
}

template <int MODE>
__global__ __launch_bounds__(256)
void gather_kernel(const ull* __restrict__ h, ull* __restrict__ out, int n)
{
    int w    = (blockIdx.x * blockDim.x + threadIdx.x) >> 5;
    int lane = threadIdx.x & 31;
    if (w >= n) return;
    int beg = g_rowptr[w], end = g_rowptr[w + 1];

    float4 acc = make_float4(0.f, 0.f, 0.f, 0.f);
    if (MODE) acc_bf(acc, h[(size_t)w * 32 + lane], 1.0f);

    int i = beg;
    for (; i + 4 <= end; i += 4) {
        int s0 = g_esrc[i], s1 = g_esrc[i + 1], s2 = g_esrc[i + 2], s3 = g_esrc[i + 3];
        ull x0 = h[(size_t)s0 * 32 + lane];
        ull x1 = h[(size_t)s1 * 32 + lane];
        ull x2 = h[(size_t)s2 * 32 + lane];
        ull x3 = h[(size_t)s3 * 32 + lane];
        float c0 = 1.f, c1 = 1.f, c2 = 1.f, c3 = 1.f;
        if (MODE) { c0 = g_rscale[i]; c1 = g_rscale[i + 1]; c2 = g_rscale[i + 2]; c3 = g_rscale[i + 3]; }
        acc_bf(acc, x0, c0);
        acc_bf(acc, x1, c1);
        acc_bf(acc, x2, c2);
        acc_bf(acc, x3, c3);
    }
    for (; i < end; i++) {
        ull x = h[(size_t)g_esrc[i] * 32 + lane];
        float c = MODE ? g_rscale[i] : 1.f;
        acc_bf(acc, x, c);
    }

    __nv_bfloat162 o0 = __floats2bfloat162_rn(acc.x, acc.y);
    __nv_bfloat162 o1 = __floats2bfloat162_rn(acc.z, acc.w);
    ull packed = (ull)*reinterpret_cast<unsigned*>(&o0)
               | ((ull)*reinterpret_cast<unsigned*>(&o1) << 32);
    out[(size_t)w * 32 + lane] = packed;
}

// ===========================================================================
// HMMA GEMM, 2-term W split: D = A_bf16 @ (Wt_hi + Wt_lo) + bias.
// (A-side bf16 quantization washes out in the 50000-node mean; the W split
// removes the systematic per-column quantization bias.)
// 128x128 tile, 256 threads, 8 warps (4m x 2n), warp tile 32x64.
// All staging via cp.async from pre-converted bf16 global buffers; uniform
// 128-row x 32-k bf16 tiles, 80B row stride (conflict-free ldmatrix);
// double-buffered, ONE __syncthreads per chunk. smem 60.5 KB -> 2 CTAs/SM.
// STORE=0 skips C store (last layer).
// ===========================================================================
#define ABUF     10240          // one 128x32 bf16 tile with 80B rows
#define OFF_A    0              // 2 stages
#define OFF_BH   (2 * ABUF)     // 2 stages
#define OFF_BL   (4 * ABUF)     // 2 stages
#define OFF_BIAS (6 * ABUF)
#define GEMM_SMEM (6 * ABUF + 512)   // 61952 bytes

template <int K, int STORE>
__global__ __launch_bounds__(256)
void gemm_mma(const __nv_bfloat16* __restrict__ A,
              const __nv_bfloat16* __restrict__ WtH,
              const __nv_bfloat16* __restrict__ WtL,
              const float* __restrict__ bias, __nv_bfloat16* __restrict__ C,
              float* __restrict__ colsum_slot, int n, int do_leaky)
{
    constexpr int NCH = K / 32;

    extern __shared__ char smem[];
    const uint32_t sb = smem_u32(smem);
    const int t    = threadIdx.x;
    const int lane = t & 31, wid = t >> 5;
    const int wr   = wid & 3, wc = wid >> 2;
    const int row0 = blockIdx.x * 128;

    if (t < 128) *reinterpret_cast<float*>(smem + OFF_BIAS + t * 4) = bias[t];

    // staging geometry: 512 16B slots per tile; thread handles slots t, t+256
    const int q   = t & 3;                 // 16B column within 64B slice
    const int sr0 = t >> 2;                // rows 0..63
    const int sr1 = 64 + sr0;              // rows 64..127
    const int ga0 = min(row0 + sr0, n - 1);
    const int ga1 = min(row0 + sr1, n - 1);

    auto stage = [&](int buf, int c) {
        // A tile
        cp16(sb + OFF_A + buf * ABUF + sr0 * 80 + q * 16,
             A + (size_t)ga0 * K + c * 32 + q * 8);
        cp16(sb + OFF_A + buf * ABUF + sr1 * 80 + q * 16,
             A + (size_t)ga1 * K + c * 32 + q * 8);
        // B hi tile
        cp16(sb + OFF_BH + buf * ABUF + sr0 * 80 + q * 16,
             WtH + (size_t)sr0 * K + c * 32 + q * 8);
        cp16(sb + OFF_BH + buf * ABUF + sr1 * 80 + q * 16,
             WtH + (size_t)sr1 * K + c * 32 + q * 8);
        // B lo tile
        cp16(sb + OFF_BL + buf * ABUF + sr0 * 80 + q * 16,
             WtL + (size_t)sr0 * K + c * 32 + q * 8);
        cp16(sb + OFF_BL + buf * ABUF + sr1 * 80 + q * 16,
             WtL + (size_t)sr1 * K + c * 32 + q * 8);
    };

    float acc[2][8][4];
#pragma unroll
    for (int i = 0; i < 2; i++)
#pragma unroll
        for (int j = 0; j < 8; j++)
#pragma unroll
            for (int p = 0; p < 4; p++) acc[i][j][p] = 0.f;

    // ldmatrix per-lane base addresses (80B row stride, conflict-free)
    const int mat = lane >> 3, lr = lane & 7;
    const uint32_t abase = (uint32_t)((wr * 32 + (mat & 1) * 8 + lr) * 80 + (mat >> 1) * 16);
    const uint32_t bbase = (uint32_t)((wc * 64 + (mat >> 1) * 8 + lr) * 80 + (mat & 1) * 16);

    // ---- pipeline ----
    stage(0, 0);
    cp_commit();

    for (int c = 0; c < NCH; c++) {
        const int cur = c & 1, nxt = cur ^ 1;
        cp_wait0();
        __syncthreads();       // chunk cur visible; all warps done with buffer nxt
        if (c + 1 < NCH) {
            stage(nxt, c + 1);
            cp_commit();
        }

        const uint32_t sA  = sb + OFF_A  + cur * ABUF + abase;
        const uint32_t sBh = sb + OFF_BH + cur * ABUF + bbase;
        const uint32_t sBl = sb + OFF_BL + cur * ABUF + bbase;
#pragma unroll
        for (int ks = 0; ks < 2; ks++) {
            unsigned a0[4], a1[4];
            ldsm4(a0, sA + ks * 32);
            ldsm4(a1, sA + 1280 + ks * 32);   // +16 rows * 80B
#pragma unroll
            for (int np = 0; np < 4; np++) {
                unsigned bh[4], bl[4];
                ldsm4(bh, sBh + np * 1280 + ks * 32);
                ldsm4(bl, sBl + np * 1280 + ks * 32);
                mma16816(acc[0][2 * np],     a0, bh);
                mma16816(acc[0][2 * np + 1], a0, bh + 2);
                mma16816(acc[1][2 * np],     a1, bh);
                mma16816(acc[1][2 * np + 1], a1, bh + 2);
                mma16816(acc[0][2 * np],     a0, bl);
                mma16816(acc[0][2 * np + 1], a0, bl + 2);
                mma16816(acc[1][2 * np],     a1, bl);
                mma16816(acc[1][2 * np + 1], a1, bl + 2);
            }
        }
    }

    // ---- epilogue: bias, leaky, bf16 store, colsum ----
    const float* sbias = reinterpret_cast<const float*>(smem + OFF_BIAS);
    float cs[8][2];
#pragma unroll
    for (int j = 0; j < 8; j++) { cs[j][0] = 0.f; cs[j][1] = 0.f; }

#pragma unroll
    for (int mt = 0; mt < 2; mt++) {
        const int r0 = row0 + wr * 32 + mt * 16 + (lane >> 2);
        const bool ok0 = (r0 < n), ok1 = (r0 + 8 < n);
#pragma unroll
        for (int nt = 0; nt < 8; nt++) {
            const int c0 = wc * 64 + nt * 8 + 2 * (lane & 3);
            float b0 = sbias[c0], b1 = sbias[c0 + 1];
            float v0 = acc[mt][nt][0] + b0;
            float v1 = acc[mt][nt][1] + b1;
            float v2 = acc[mt][nt][2] + b0;
            float v3 = acc[mt][nt][3] + b1;
            if (do_leaky) {
                v0 = v0 > 0.f ? v0 : 0.01f * v0;
                v1 = v1 > 0.f ? v1 : 0.01f * v1;
                v2 = v2 > 0.f ? v2 : 0.01f * v2;
                v3 = v3 > 0.f ? v3 : 0.01f * v3;
            }
            if (!ok0) { v0 = 0.f; v1 = 0.f; }
            if (!ok1) { v2 = 0.f; v3 = 0.f; }
            cs[nt][0] += v0 + v2;
            cs[nt][1] += v1 + v3;
            if (STORE) {
                if (ok0)
                    *reinterpret_cast<__nv_bfloat162*>(C + (size_t)r0 * HD + c0) =
                        __floats2bfloat162_rn(v0, v1);
                if (ok1)
                    *reinterpret_cast<__nv_bfloat162*>(C + (size_t)(r0 + 8) * HD + c0) =
                        __floats2bfloat162_rn(v2, v3);
            }
        }
    }

    // colsum: shfl-reduce over row-groups, then per-wr smem rows (warps wc=0/1
    // write disjoint column halves -> all 4x128 entries valid)
#pragma unroll
    for (int nt = 0; nt < 8; nt++) {
#pragma unroll
        for (int off = 4; off < 32; off <<= 1) {
            cs[nt][0] += __shfl_xor_sync(0xFFFFFFFFu, cs[nt][0], off);
            cs[nt][1] += __shfl_xor_sync(0xFFFFFFFFu, cs[nt][1], off);
        }
    }
    __syncthreads();
    float* sred = reinterpret_cast<float*>(smem + OFF_A);   // reuse A buffers
    if (lane < 4) {
#pragma unroll
        for (int nt = 0; nt < 8; nt++) {
            int c0 = wc * 64 + nt * 8 + 2 * lane;
            sred[wr * 128 + c0]     = cs[nt][0];
            sred[wr * 128 + c0 + 1] = cs[nt][1];
        }
    }
    __syncthreads();
    if (t < 128) {
        float s = 0.f;
#pragma unroll
        for (int r = 0; r < 4; r++) s += sred[r * 128 + t];
        atomicAdd(&colsum_slot[t], s);
    }
}

// ---------------------------------------------------------------------------
// Readout: g = (colsum/N) @ Wpred + bpred ; logits = g @ Wcls + bcls ; softmax
// ---------------------------------------------------------------------------
__global__ void final_kernel(const float* __restrict__ colsum,
                             const float* __restrict__ Wpred, const float* __restrict__ bpred,
                             const float* __restrict__ Wcls,  const float* __restrict__ bcls,
                             float* __restrict__ out, float invn)
{
    __shared__ float g[HD];
    int t = threadIdx.x;
    float acc = bpred[t];
    for (int k = 0; k < (NL + 1) * HD; k++)
        acc = fmaf(colsum[k] * invn, Wpred[k * HD + t], acc);
    g[t] = acc;
    __syncthreads();
    if (t == 0) {
        float l0 = bcls[0], l1 = bcls[1];
        for (int j = 0; j < HD; j++) {
            l0 = fmaf(g[j], Wcls[j * 2 + 0], l0);
            l1 = fmaf(g[j], Wcls[j * 2 + 1], l1);
        }
        float m  = fmaxf(l0, l1);
        float e0 = expf(l0 - m), e1 = expf(l1 - m);
        float inv = 1.0f / (e0 + e1);
        out[0] = e0 * inv;
        out[1] = e1 * inv;
    }
}

// ---------------------------------------------------------------------------
extern "C" void kernel_launch(void* const* d_in, const int* in_sizes, int n_in,
                              void* d_out, int out_size)
{
    const float* node_feat = (const float*)d_in[0];
    const float* degree    = (const float*)d_in[3];
    const float* Wn        = (const float*)d_in[4];
    const float* bn        = (const float*)d_in[5];
    const float* Wgcn      = (const float*)d_in[8];
    const float* bgcn      = (const float*)d_in[9];
    const float* Wpred     = (const float*)d_in[10];
    const float* bpred     = (const float*)d_in[11];
    const float* Wcls      = (const float*)d_in[12];
    const float* bcls      = (const float*)d_in[13];
    const int*   src       = (const int*)d_in[14];
    const int*   dst       = (const int*)d_in[15];

    const int n = in_sizes[3];
    const int e = in_sizes[14];

    float *CS;
    __nv_bfloat16 *NF16, *AG, *H0, *H1, *WTNH, *WTNL, *WTGH, *WTGL;
    int *CNT;
    cudaGetSymbolAddress((void**)&NF16, g_nf16);
    cudaGetSymbolAddress((void**)&AG,   g_agg);
    cudaGetSymbolAddress((void**)&H0,   g_h0);
    cudaGetSymbolAddress((void**)&H1,   g_h1);
    cudaGetSymbolAddress((void**)&WTNH, g_wtnh);
    cudaGetSymbolAddress((void**)&WTNL, g_wtnl);
    cudaGetSymbolAddress((void**)&WTGH, g_wtgh);
    cudaGetSymbolAddress((void**)&WTGL, g_wtgl);
    cudaGetSymbolAddress((void**)&CS,   g_colsum);
    cudaGetSymbolAddress((void**)&CNT,  g_cnt);

    static bool init_done = false;
    static cudaStream_t s2;
    static cudaEvent_t ev_fork, ev_join;
    if (!init_done) {
        cudaFuncSetAttribute(gemm_mma<NFK, 1>, cudaFuncAttributeMaxDynamicSharedMemorySize, GEMM_SMEM);
        cudaFuncSetAttribute(gemm_mma<HD, 1>,  cudaFuncAttributeMaxDynamicSharedMemorySize, GEMM_SMEM);
        cudaFuncSetAttribute(gemm_mma<HD, 0>,  cudaFuncAttributeMaxDynamicSharedMemorySize, GEMM_SMEM);
        cudaStreamCreateWithFlags(&s2, cudaStreamNonBlocking);
        cudaEventCreateWithFlags(&ev_fork, cudaEventDisableTiming);
        cudaEventCreateWithFlags(&ev_join, cudaEventDisableTiming);
        init_done = true;
    }

    const int gemm_blocks   = (n + 127) / 128;
    const int edge_blocks   = (e + 255) / 256;
    const int gather_blocks = (n + 7) / 8;

    // ---- fork: CSR build on s2, overlapped with prep + input GEMM ----
    cudaEventRecord(ev_fork, 0);
    cudaStreamWaitEvent(s2, ev_fork, 0);

    cudaMemsetAsync(CNT, 0, NN * sizeof(int), s2);
    hist_kernel<<<edge_blocks, 256, 0, s2>>>(dst, e);
    scan_kernel<<<1, 1024, 0, s2>>>(n);
    fill_kernel<<<edge_blocks, 256, 0, s2>>>(src, dst, degree, e);
    cudaEventRecord(ev_join, s2);

    // main stream: prep (W transpose/split, node_feat bf16), then gemm256
    cudaMemsetAsync(CS, 0, (NL + 1) * HD * sizeof(float));
    prepw_kernel<<<(128 * NFK + 255) / 256, 256>>>(Wn, WTNH, WTNL, NFK);
    prepw_kernel<<<(128 * HD + 255) / 256, 256>>>(Wgcn, WTGH, WTGL, HD);
    cvt_kernel<<<(n * NFK / 8 + 255) / 256, 256>>>(node_feat, NF16, n * NFK / 8);

    // h0 = node_feat @ Wn + bn -> H0 (bf16); colsum slot 0
    gemm_mma<NFK, 1><<<gemm_blocks, 256, GEMM_SMEM>>>(
        NF16, WTNH, WTNL, bn, H0, CS, n, 0);

    // join: gathers need both the CSR and H0
    cudaStreamWaitEvent(0, ev_join, 0);

    // fusion: H1[v] = sum_{u->v} h0[u]
    gather_kernel<0><<<gather_blocks, 256>>>((const ull*)H0, (ull*)H1, n);

    // layer 0: gather H1 -> AG (bf16), gemm AG -> H0
    gather_kernel<1><<<gather_blocks, 256>>>((const ull*)H1, (ull*)AG, n);
    gemm_mma<HD, 1><<<gemm_blocks, 256, GEMM_SMEM>>>(
        AG, WTGH, WTGL, bgcn, H0, CS + 1 * HD, n, 1);

    // layer 1: gather H0 -> AG, gemm AG -> H1
    gather_kernel<1><<<gather_blocks, 256>>>((const ull*)H0, (ull*)AG, n);
    gemm_mma<HD, 1><<<gemm_blocks, 256, GEMM_SMEM>>>(
        AG, WTGH, WTGL, bgcn, H1, CS + 2 * HD, n, 1);

    // layer 2: gather H1 -> AG, gemm colsum-only (h3 never read again)
    gather_kernel<1><<<gather_blocks, 256>>>((const ull*)H1, (ull*)AG, n);
    gemm_mma<HD, 0><<<gemm_blocks, 256, GEMM_SMEM>>>(
        AG, WTGH, WTGL, bgcn, (__nv_bfloat16*)nullptr, CS + 3 * HD, n, 1);

    final_kernel<<<1, HD>>>(CS, Wpred, bpred, Wcls, bcls, (float*)d_out, 1.0f / (float)n);
}

// round 13
// speedup vs baseline: 1.1142x; 1.1142x over previous
#include <cuda_runtime.h>
#include <cuda_bf16.h>
#include <cstdint>

// Problem constants (fixed by the dataset)
#define NN   50000
#define EE   800000
#define NFK  256
#define HD   128
#define NL   3

typedef unsigned long long ull;

// Scratch: static device arrays (no runtime allocation allowed)
__device__ __align__(16) float g_bufA[NN * HD];             // fp32 agg (25.6 MB)
__device__ __align__(16) __nv_bfloat16 g_h0[NN * HD];       // bf16 h ping (12.8 MB)
__device__ __align__(16) __nv_bfloat16 g_h1[NN * HD];       // bf16 h pong (12.8 MB)
__device__ float g_colsum[(NL + 1) * HD];                   // 512 floats
// CSR scratch
__device__ int   g_cnt[NN];
__device__ int   g_rowptr[NN + 1];
__device__ int   g_offs[NN];
__device__ int   g_esrc[EE];
__device__ float g_rscale[EE];

// Packed fp32x2 FMA (Blackwell): d = a*b + d elementwise on 2 packed floats.
__device__ __forceinline__ void ffma2(ull& d, ull a, ull b)
{
    asm("fma.rn.f32x2 %0, %1, %2, %3;" : "=l"(d) : "l"(a), "l"(b), "l"(d));
}

// cp.async 16B global->shared
__device__ __forceinline__ void cp16(void* smem, const void* g)
{
    unsigned sa = (unsigned)__cvta_generic_to_shared(smem);
    asm volatile("cp.async.cg.shared.global [%0], [%1], 16;" :: "r"(sa), "l"(g));
}
__device__ __forceinline__ void cp_commit() { asm volatile("cp.async.commit_group;"); }
__device__ __forceinline__ void cp_wait0()  { asm volatile("cp.async.wait_group 0;" ::: "memory"); }

// ---------------------------------------------------------------------------
// CSR build (per replay; order within a dst bucket is arbitrary)
// ---------------------------------------------------------------------------
__global__ void hist_kernel(const int* __restrict__ dst, int e)
{
    int i = blockIdx.x * blockDim.x + threadIdx.x;
    if (i < e) atomicAdd(&g_cnt[dst[i]], 1);
}

__global__ __launch_bounds__(1024)
void scan_kernel(int n)
{
    __shared__ int part[1024];
    int t = threadIdx.x;
    int chunk = (n + 1023) >> 10;
    int beg = t * chunk, end = min(beg + chunk, n);
    int s = 0;
    for (int i = beg; i < end; i++) s += g_cnt[i];
    part[t] = s;
    __syncthreads();
    for (int off = 1; off < 1024; off <<= 1) {
        int v = (t >= off) ? part[t - off] : 0;
        __syncthreads();
        part[t] += v;
        __syncthreads();
    }
    int run = part[t] - s;
    for (int i = beg; i < end; i++) {
        g_rowptr[i] = run;
        g_offs[i]   = run;
        run += g_cnt[i];
    }
    if (end == n) g_rowptr[n] = run;
}

__global__ void fill_kernel(const int* __restrict__ src, const int* __restrict__ dst,
                            const float* __restrict__ degree, int e)
{
    int i = blockIdx.x * blockDim.x + threadIdx.x;
    if (i >= e) return;
    int s = src[i], d = dst[i];
    int pos = atomicAdd(&g_offs[d], 1);
    g_esrc[pos]   = s;
    g_rscale[pos] = 1.0f / degree[s];
}

// ---------------------------------------------------------------------------
// Gather over bf16 hidden states, fp32 accumulation.
// MODE 0: out_bf16[v] = sum_{u->v} h[u]
// MODE 1: out_f32[v]  = h[v] + sum_{u->v} h[u] * (1/deg[u])
// One warp per node; lane owns 4 columns (LDG.64 per edge).
// 8-wide unroll: 8 independent row-loads in flight to hide L2 latency.
// ---------------------------------------------------------------------------
__device__ __forceinline__ void acc_bf(float4& acc, ull x, float c)
{
    const __nv_bfloat162* p = reinterpret_cast<const __nv_bfloat162*>(&x);
    float2 f0 = __bfloat1622float2(p[0]);
    float2 f1 = __bfloat1622float2(p[1]);
    acc.x = fmaf(f0.x, c, acc.x); acc.y = fmaf(f0.y, c, acc.y);
    acc.z = fmaf(f1.x, c, acc.z); acc.w = fmaf(f1.y, c, acc.w);
}

template <int MODE>
__global__ __launch_bounds__(256)
void gather_kernel(const ull* __restrict__ h, void* __restrict__ out_, int n)
{
    int w    = (blockIdx.x * blockDim.x + threadIdx.x) >> 5;
    int lane = threadIdx.x & 31;
    if (w >= n) return;
    int beg = g_rowptr[w], end = g_rowptr[w + 1];

    float4 acc = make_float4(0.f, 0.f, 0.f, 0.f);
    if (MODE) {
        ull sv = h[(size_t)w * 32 + lane];
        acc_bf(acc, sv, 1.0f);
    }

    int i = beg;
    // 8-wide unrolled main loop: batch indices, then 8 gathers in flight
    for (; i + 8 <= end; i += 8) {
        int  sidx[8];
        ull  x[8];
        float c[8];
#pragma unroll
        for (int j = 0; j < 8; j++) sidx[j] = g_esrc[i + j];
#pragma unroll
        for (int j = 0; j < 8; j++) x[j] = h[(size_t)sidx[j] * 32 + lane];
        if (MODE) {
#pragma unroll
            for (int j = 0; j < 8; j++) c[j] = g_rscale[i + j];
        } else {
#pragma unroll
            for (int j = 0; j < 8; j++) c[j] = 1.f;
        }
#pragma unroll
        for (int j = 0; j < 8; j++) acc_bf(acc, x[j], c[j]);
    }
    // 4-wide tail
    for (; i + 4 <= end; i += 4) {
        int s0 = g_esrc[i], s1 = g_esrc[i + 1], s2 = g_esrc[i + 2], s3 = g_esrc[i + 3];
        ull x0 = h[(size_t)s0 * 32 + lane];
        ull x1 = h[(size_t)s1 * 32 + lane];
        ull x2 = h[(size_t)s2 * 32 + lane];
        ull x3 = h[(size_t)s3 * 32 + lane];
        float c0 = 1.f, c1 = 1.f, c2 = 1.f, c3 = 1.f;
        if (MODE) { c0 = g_rscale[i]; c1 = g_rscale[i + 1]; c2 = g_rscale[i + 2]; c3 = g_rscale[i + 3]; }
        acc_bf(acc, x0, c0);
        acc_bf(acc, x1, c1);
        acc_bf(acc, x2, c2);
        acc_bf(acc, x3, c3);
    }
    for (; i < end; i++) {
        ull x = h[(size_t)g_esrc[i] * 32 + lane];
        float c = MODE ? g_rscale[i] : 1.f;
        acc_bf(acc, x, c);
    }

    if (MODE) {
        // fp32 output (GEMM input)
        reinterpret_cast<float4*>(out_)[(size_t)w * 32 + lane] = acc;
    } else {
        // bf16 output
        __nv_bfloat162 o0 = __floats2bfloat162_rn(acc.x, acc.y);
        __nv_bfloat162 o1 = __floats2bfloat162_rn(acc.z, acc.w);
        ull packed = (ull)*reinterpret_cast<unsigned*>(&o0)
                   | ((ull)*reinterpret_cast<unsigned*>(&o1) << 32);
        reinterpret_cast<ull*>(out_)[(size_t)w * 32 + lane] = packed;
    }
}

// ---------------------------------------------------------------------------
// GEMM: C_bf16[n x 128] = A_f32[n x K] @ W[K x 128] + bias, optional leaky,
// fused per-column sum (computed from fp32 pre-quantization values).
// Tile 128x128, 256 threads, thread = 8 rows x 8 cols (column PAIRS at
// {2tx+32j, 2tx+32j+1}); wv loads conflict-free 128B-contiguous; av loads
// LDS.128 covering 2 k-steps. Double-buffered (cp.async W, reg-prefetch A).
// STORE=0 skips the C store (last layer: only colsum needed).
// ---------------------------------------------------------------------------
#define SW_FLOATS (16 * 128)
#define SA_PAIRS  (128 * 20)
#define GEMM_SMEM (2 * SW_FLOATS * 4 + 2 * SA_PAIRS * 8)   // 57344 bytes

template <int K, int STORE>
__global__ __launch_bounds__(256, 2)
void gemm_kernel(const float* __restrict__ A, const float* __restrict__ W,
                 const float* __restrict__ bias, __nv_bfloat16* __restrict__ C,
                 float* __restrict__ colsum_slot, int n, int do_leaky)
{
    extern __shared__ float smem_dyn[];
    float*  sW = smem_dyn;                            // 2 x 2048 floats
    float2* sA = (float2*)(smem_dyn + 2 * SW_FLOATS); // 2 x 2560 float2

    const int t    = threadIdx.x;
    const int tx   = t & 15;               // column pairs {2tx+32j, 2tx+32j+1}
    const int ty   = t >> 4;               // 0..15: rows [8*ty, 8*ty+7]
    const int row0 = blockIdx.x * 128;
    constexpr int NC = K / 16;

    // A staging geometry: thread stages two float4 (512 slots)
    const int f0 = t,       r0 = f0 >> 2, kv0 = (f0 & 3) * 4;
    const int f1 = t + 256, r1 = f1 >> 2, kv1 = (f1 & 3) * 4;
    const int grow0 = row0 + r0, grow1 = row0 + r1;

    ull acc[8][4];
#pragma unroll
    for (int i = 0; i < 8; i++)
#pragma unroll
        for (int j = 0; j < 4; j++) acc[i][j] = 0ull;

    // ---- prologue: stage chunk 0 ----
    {
        const float4* Wv = reinterpret_cast<const float4*>(W);
        cp16(&reinterpret_cast<float4*>(sW)[t], Wv + t);
        cp16(&reinterpret_cast<float4*>(sW)[t + 256], Wv + t + 256);
        cp_commit();
        float4 v0 = make_float4(0, 0, 0, 0), v1 = make_float4(0, 0, 0, 0);
        if (grow0 < n) v0 = *reinterpret_cast<const float4*>(A + (size_t)grow0 * K + kv0);
        if (grow1 < n) v1 = *reinterpret_cast<const float4*>(A + (size_t)grow1 * K + kv1);
        float2* dp0 = &sA[r0 * 20];
        dp0[kv0 + 0] = make_float2(v0.x, v0.x); dp0[kv0 + 1] = make_float2(v0.y, v0.y);
        dp0[kv0 + 2] = make_float2(v0.z, v0.z); dp0[kv0 + 3] = make_float2(v0.w, v0.w);
        float2* dp1 = &sA[r1 * 20];
        dp1[kv1 + 0] = make_float2(v1.x, v1.x); dp1[kv1 + 1] = make_float2(v1.y, v1.y);
        dp1[kv1 + 2] = make_float2(v1.z, v1.z); dp1[kv1 + 3] = make_float2(v1.w, v1.w);
        cp_wait0();
        __syncthreads();
    }

    for (int c = 0; c < NC; c++) {
        const int cur = c & 1, nxt = cur ^ 1;
        float4 v0, v1;
        const bool pre = (c + 1 < NC);
        if (pre) {
            const int k0n = (c + 1) * 16;
            const float4* Wv = reinterpret_cast<const float4*>(W + (size_t)k0n * HD);
            float4* sWn = reinterpret_cast<float4*>(sW + nxt * SW_FLOATS);
            cp16(&sWn[t], Wv + t);
            cp16(&sWn[t + 256], Wv + t + 256);
            cp_commit();
            v0 = make_float4(0, 0, 0, 0); v1 = make_float4(0, 0, 0, 0);
            if (grow0 < n) v0 = *reinterpret_cast<const float4*>(A + (size_t)grow0 * K + k0n + kv0);
            if (grow1 < n) v1 = *reinterpret_cast<const float4*>(A + (size_t)grow1 * K + k0n + kv1);
        }

        // ---- compute chunk 'cur' (2 k-steps per iteration) ----
        const float*  sWc = sW + cur * SW_FLOATS;
        const float2* sAc = sA + cur * SA_PAIRS;
#pragma unroll
        for (int kk = 0; kk < 16; kk += 2) {
            ull wv0[4], wv1[4];
#pragma unroll
            for (int j = 0; j < 4; j++) {
                wv0[j] = *reinterpret_cast<const ull*>(&sWc[kk * 128 + 2 * tx + 32 * j]);
                wv1[j] = *reinterpret_cast<const ull*>(&sWc[(kk + 1) * 128 + 2 * tx + 32 * j]);
            }
#pragma unroll
            for (int i = 0; i < 8; i++) {
                ulonglong2 av = *reinterpret_cast<const ulonglong2*>(
                                    &sAc[(ty * 8 + i) * 20 + kk]);
#pragma unroll
                for (int j = 0; j < 4; j++) ffma2(acc[i][j], av.x, wv0[j]);
#pragma unroll
                for (int j = 0; j < 4; j++) ffma2(acc[i][j], av.y, wv1[j]);
            }
        }

        if (pre) {
            float2* dp0 = &sA[nxt * SA_PAIRS + r0 * 20];
            dp0[kv0 + 0] = make_float2(v0.x, v0.x); dp0[kv0 + 1] = make_float2(v0.y, v0.y);
            dp0[kv0 + 2] = make_float2(v0.z, v0.z); dp0[kv0 + 3] = make_float2(v0.w, v0.w);
            float2* dp1 = &sA[nxt * SA_PAIRS + r1 * 20];
            dp1[kv1 + 0] = make_float2(v1.x, v1.x); dp1[kv1 + 1] = make_float2(v1.y, v1.y);
            dp1[kv1 + 2] = make_float2(v1.z, v1.z); dp1[kv1 + 3] = make_float2(v1.w, v1.w);
            cp_wait0();
            __syncthreads();
        }
    }

    // ---- epilogue: bias, activation, bf16 store, colsum (fp32) ----
    float2 b[4];
#pragma unroll
    for (int j = 0; j < 4; j++)
        b[j] = *reinterpret_cast<const float2*>(&bias[2 * tx + 32 * j]);

    float2 cs[4];
#pragma unroll
    for (int j = 0; j < 4; j++) cs[j] = make_float2(0.f, 0.f);

#pragma unroll
    for (int i = 0; i < 8; i++) {
        int row = row0 + ty * 8 + i;
        if (row < n) {
#pragma unroll
            for (int j = 0; j < 4; j++) {
                float2 a2 = *reinterpret_cast<float2*>(&acc[i][j]);
                float2 vv;
                vv.x = a2.x + b[j].x;
                vv.y = a2.y + b[j].y;
                if (do_leaky) {
                    vv.x = vv.x > 0.f ? vv.x : 0.01f * vv.x;
                    vv.y = vv.y > 0.f ? vv.y : 0.01f * vv.y;
                }
                cs[j].x += vv.x;
                cs[j].y += vv.y;
                if (STORE) {
                    *reinterpret_cast<__nv_bfloat162*>(
                        C + (size_t)row * HD + 2 * tx + 32 * j) =
                        __floats2bfloat162_rn(vv.x, vv.y);
                }
            }
        }
    }

    // block-level colsum reduction: sred[16][128] floats (reuse sW buffers)
    __syncthreads();
    float* sred = sW;
#pragma unroll
    for (int j = 0; j < 4; j++) {
        sred[ty * 128 + 2 * tx + 32 * j]     = cs[j].x;
        sred[ty * 128 + 2 * tx + 32 * j + 1] = cs[j].y;
    }
    __syncthreads();
    if (t < 128) {
        float s = 0.f;
#pragma unroll
        for (int r = 0; r < 16; r++) s += sred[r * 128 + t];
        atomicAdd(&colsum_slot[t], s);
    }
}

// ---------------------------------------------------------------------------
// Readout: g = (colsum/N) @ Wpred + bpred ; logits = g @ Wcls + bcls ; softmax
// ---------------------------------------------------------------------------
__global__ void final_kernel(const float* __restrict__ colsum,
                             const float* __restrict__ Wpred, const float* __restrict__ bpred,
                             const float* __restrict__ Wcls,  const float* __restrict__ bcls,
                             float* __restrict__ out, float invn)
{
    __shared__ float g[HD];
    int t = threadIdx.x;
    float acc = bpred[t];
    for (int k = 0; k < (NL + 1) * HD; k++)
        acc = fmaf(colsum[k] * invn, Wpred[k * HD + t], acc);
    g[t] = acc;
    __syncthreads();
    if (t == 0) {
        float l0 = bcls[0], l1 = bcls[1];
        for (int j = 0; j < HD; j++) {
            l0 = fmaf(g[j], Wcls[j * 2 + 0], l0);
            l1 = fmaf(g[j], Wcls[j * 2 + 1], l1);
        }
        float m  = fmaxf(l0, l1);
        float e0 = expf(l0 - m), e1 = expf(l1 - m);
        float inv = 1.0f / (e0 + e1);
        out[0] = e0 * inv;
        out[1] = e1 * inv;
    }
}

// ---------------------------------------------------------------------------
extern "C" void kernel_launch(void* const* d_in, const int* in_sizes, int n_in,
                              void* d_out, int out_size)
{
    const float* node_feat = (const float*)d_in[0];
    const float* degree    = (const float*)d_in[3];
    const float* Wn        = (const float*)d_in[4];
    const float* bn        = (const float*)d_in[5];
    const float* Wgcn      = (const float*)d_in[8];
    const float* bgcn      = (const float*)d_in[9];
    const float* Wpred     = (const float*)d_in[10];
    const float* bpred     = (const float*)d_in[11];
    const float* Wcls      = (const float*)d_in[12];
    const float* bcls      = (const float*)d_in[13];
    const int*   src       = (const int*)d_in[14];
    const int*   dst       = (const int*)d_in[15];

    const int n = in_sizes[3];
    const int e = in_sizes[14];

    float *AG, *CS;
    __nv_bfloat16 *H0, *H1;
    int *CNT;
    cudaGetSymbolAddress((void**)&AG,  g_bufA);
    cudaGetSymbolAddress((void**)&H0,  g_h0);
    cudaGetSymbolAddress((void**)&H1,  g_h1);
    cudaGetSymbolAddress((void**)&CS,  g_colsum);
    cudaGetSymbolAddress((void**)&CNT, g_cnt);

    static bool init_done = false;
    static cudaStream_t s2;
    static cudaEvent_t ev_fork, ev_join;
    if (!init_done) {
        cudaFuncSetAttribute(gemm_kernel<NFK, 1>, cudaFuncAttributeMaxDynamicSharedMemorySize, GEMM_SMEM);
        cudaFuncSetAttribute(gemm_kernel<HD, 1>,  cudaFuncAttributeMaxDynamicSharedMemorySize, GEMM_SMEM);
        cudaFuncSetAttribute(gemm_kernel<HD, 0>,  cudaFuncAttributeMaxDynamicSharedMemorySize, GEMM_SMEM);
        cudaStreamCreateWithFlags(&s2, cudaStreamNonBlocking);
        cudaEventCreateWithFlags(&ev_fork, cudaEventDisableTiming);
        cudaEventCreateWithFlags(&ev_join, cudaEventDisableTiming);
        init_done = true;
    }

    const int gemm_blocks   = (n + 127) / 128;
    const int edge_blocks   = (e + 255) / 256;
    const int gather_blocks = (n + 7) / 8;

    // ---- fork: CSR build on s2, overlapped with the big input GEMM ----
    cudaEventRecord(ev_fork, 0);
    cudaStreamWaitEvent(s2, ev_fork, 0);

    cudaMemsetAsync(CNT, 0, NN * sizeof(int), s2);
    hist_kernel<<<edge_blocks, 256, 0, s2>>>(dst, e);
    scan_kernel<<<1, 1024, 0, s2>>>(n);
    fill_kernel<<<edge_blocks, 256, 0, s2>>>(src, dst, degree, e);
    cudaEventRecord(ev_join, s2);

    // main stream: colsum zero + h0 = node_feat @ Wn + bn -> H0 (bf16)
    cudaMemsetAsync(CS, 0, (NL + 1) * HD * sizeof(float));
    gemm_kernel<NFK, 1><<<gemm_blocks, 256, GEMM_SMEM>>>(node_feat, Wn, bn, H0, CS, n, 0);

    // join: gathers need both the CSR and H0
    cudaStreamWaitEvent(0, ev_join, 0);

    // fusion: H1[v] = sum_{u->v} h0[u]   (bf16 -> bf16)
    gather_kernel<0><<<gather_blocks, 256>>>((const ull*)H0, H1, n);

    // layer 0: gather H1 -> AG (fp32), gemm AG -> H0 (bf16)
    gather_kernel<1><<<gather_blocks, 256>>>((const ull*)H1, AG, n);
    gemm_kernel<HD, 1><<<gemm_blocks, 256, GEMM_SMEM>>>(AG, Wgcn, bgcn, H0, CS + 1 * HD, n, 1);

    // layer 1: gather H0 -> AG, gemm AG -> H1
    gather_kernel<1><<<gather_blocks, 256>>>((const ull*)H0, AG, n);
    gemm_kernel<HD, 1><<<gemm_blocks, 256, GEMM_SMEM>>>(AG, Wgcn, bgcn, H1, CS + 2 * HD, n, 1);

    // layer 2: gather H1 -> AG, gemm colsum-only (h3 never read again)
    gather_kernel<1><<<gather_blocks, 256>>>((const ull*)H1, AG, n);
    gemm_kernel<HD, 0><<<gemm_blocks, 256, GEMM_SMEM>>>(AG, Wgcn, bgcn, (__nv_bfloat16*)nullptr, CS + 3 * HD, n, 1);

    final_kernel<<<1, HD>>>(CS, Wpred, bpred, Wcls, bcls, (float*)d_out, 1.0f / (float)n);
}

// round 14
// speedup vs baseline: 1.7084x; 1.5334x over previous
#include <cuda_runtime.h>
#include <cuda_bf16.h>
#include <cstdint>

// Problem constants (fixed by the dataset)
#define NN   50000
#define EE   800000
#define NFK  256
#define HD   128
#define NL   3

typedef unsigned long long ull;

// Scratch: static device arrays (no runtime allocation allowed)
__device__ __align__(16) __nv_bfloat16 g_agg[NN * HD];    // bf16 GEMM input
__device__ __align__(16) __nv_bfloat16 g_h0[NN * HD];     // bf16 h ping
__device__ __align__(16) __nv_bfloat16 g_h1[NN * HD];     // bf16 h pong
__device__ __align__(16) __nv_bfloat16 g_wtnh[128 * NFK]; // Wn^T hi
__device__ __align__(16) __nv_bfloat16 g_wtnl[128 * NFK]; // Wn^T lo
__device__ __align__(16) __nv_bfloat16 g_wtgh[128 * HD];  // Wgcn^T hi
__device__ __align__(16) __nv_bfloat16 g_wtgl[128 * HD];  // Wgcn^T lo
__device__ float g_colsum[(NL + 1) * HD];                 // 512 floats
// CSR scratch
__device__ int   g_cnt[NN];
__device__ int   g_rowptr[NN + 1];
__device__ int   g_offs[NN];
__device__ int   g_esrc[EE];
__device__ float g_rscale[EE];

// ---------------------------------------------------------------------------
// low-level helpers
// ---------------------------------------------------------------------------
__device__ __forceinline__ uint32_t smem_u32(const void* p) {
    uint32_t a;
    asm("{ .reg .u64 tmp; cvta.to.shared.u64 tmp, %1; cvt.u32.u64 %0, tmp; }"
        : "=r"(a) : "l"(p));
    return a;
}
__device__ __forceinline__ void cp16(uint32_t smem_addr, const void* g)
{
    asm volatile("cp.async.cg.shared.global [%0], [%1], 16;" :: "r"(smem_addr), "l"(g));
}
__device__ __forceinline__ void cp_commit() { asm volatile("cp.async.commit_group;"); }
__device__ __forceinline__ void cp_wait0()  { asm volatile("cp.async.wait_group 0;" ::: "memory"); }

__device__ __forceinline__ void ldsm4(unsigned* r, uint32_t addr) {
    asm volatile("ldmatrix.sync.aligned.m8n8.x4.shared.b16 {%0,%1,%2,%3}, [%4];"
        : "=r"(r[0]), "=r"(r[1]), "=r"(r[2]), "=r"(r[3]) : "r"(addr));
}
__device__ __forceinline__ void mma16816(float* c, const unsigned* a, const unsigned* b) {
    asm volatile("mma.sync.aligned.m16n8k16.row.col.f32.bf16.bf16.f32 "
        "{%0,%1,%2,%3}, {%4,%5,%6,%7}, {%8,%9}, {%0,%1,%2,%3};"
        : "+f"(c[0]), "+f"(c[1]), "+f"(c[2]), "+f"(c[3])
        : "r"(a[0]), "r"(a[1]), "r"(a[2]), "r"(a[3]), "r"(b[0]), "r"(b[1]));
}
__device__ __forceinline__ unsigned pk_hi(float a, float b) {
    __nv_bfloat162 p = __floats2bfloat162_rn(a, b);
    return *reinterpret_cast<unsigned*>(&p);
}

// ---------------------------------------------------------------------------
// Prep: W[k][n] fp32 -> Wt_hi[n][k], Wt_lo[n][k] bf16 (hi/lo split)
// ---------------------------------------------------------------------------
__global__ void prepw_kernel(const float* __restrict__ W,
                             __nv_bfloat16* __restrict__ WtH,
                             __nv_bfloat16* __restrict__ WtL, int K)
{
    int i = blockIdx.x * blockDim.x + threadIdx.x;
    if (i >= 128 * K) return;
    int n = i / K, k = i - n * K;
    float v = W[k * 128 + n];
    __nv_bfloat16 h = __float2bfloat16_rn(v);
    WtH[i] = h;
    WtL[i] = __float2bfloat16_rn(v - __bfloat162float(h));
}

// ---------------------------------------------------------------------------
// CSR build (per replay; order within a dst bucket is arbitrary)
// ---------------------------------------------------------------------------
__global__ void hist_kernel(const int* __restrict__ dst, int e)
{
    int i = blockIdx.x * blockDim.x + threadIdx.x;
    if (i < e) atomicAdd(&g_cnt[dst[i]], 1);
}

__global__ __launch_bounds__(1024)
void scan_kernel(int n)
{
    __shared__ int part[1024];
    int t = threadIdx.x;
    int chunk = (n + 1023) >> 10;
    int beg = t * chunk, end = min(beg + chunk, n);
    int s = 0;
    for (int i = beg; i < end; i++) s += g_cnt[i];
    part[t] = s;
    __syncthreads();
    for (int off = 1; off < 1024; off <<= 1) {
        int v = (t >= off) ? part[t - off] : 0;
        __syncthreads();
        part[t] += v;
        __syncthreads();
    }
    int run = part[t] - s;
    for (int i = beg; i < end; i++) {
        g_rowptr[i] = run;
        g_offs[i]   = run;
        run += g_cnt[i];
    }
    if (end == n) g_rowptr[n] = run;
}

__global__ void fill_kernel(const int* __restrict__ src, const int* __restrict__ dst,
                            const float* __restrict__ degree, int e)
{
    int i = blockIdx.x * blockDim.x + threadIdx.x;
    if (i >= e) return;
    int s = src[i], d = dst[i];
    int pos = atomicAdd(&g_offs[d], 1);
    g_esrc[pos]   = s;
    g_rscale[pos] = 1.0f / degree[s];
}

// ---------------------------------------------------------------------------
// Gather over bf16 hidden states, fp32 accumulation, bf16 output.
// MODE 0: out[v] = sum_{u->v} h[u]
// MODE 1: out[v] = h[v] + sum_{u->v} h[u] * (1/deg[u])
// 8-wide unroll for MLP.
// ---------------------------------------------------------------------------
__device__ __forceinline__ void acc_bf(float4& acc, ull x, float c)
{
    const __nv_bfloat162* p = reinterpret_cast<const __nv_bfloat162*>(&x);
    float2 f0 = __bfloat1622float2(p[0]);
    float2 f1 = __bfloat1622float2(p[1]);
    acc.x = fmaf(f0.x, c, acc.x); acc.y = fmaf(f0.y, c, acc.y);
    acc.z = fmaf(f1.x, c, acc.z); acc.w = fmaf(f1.y, c, acc.w);
}

template <int MODE>
__global__ __launch_bounds__(256)
void gather_kernel(const ull* __restrict__ h, ull* __restrict__ out, int n)
{
    int w    = (blockIdx.x * blockDim.x + threadIdx.x) >> 5;
    int lane = threadIdx.x & 31;
    if (w >= n) return;
    int beg = g_rowptr[w], end = g_rowptr[w + 1];

    float4 acc = make_float4(0.f, 0.f, 0.f, 0.f);
    if (MODE) acc_bf(acc, h[(size_t)w * 32 + lane], 1.0f);

    int i = beg;
    for (; i + 8 <= end; i += 8) {
        int  sidx[8];
        ull  x[8];
        float c[8];
#pragma unroll
        for (int j = 0; j < 8; j++) sidx[j] = g_esrc[i + j];
#pragma unroll
        for (int j = 0; j < 8; j++) x[j] = h[(size_t)sidx[j] * 32 + lane];
        if (MODE) {
#pragma unroll
            for (int j = 0; j < 8; j++) c[j] = g_rscale[i + j];
        } else {
#pragma unroll
            for (int j = 0; j < 8; j++) c[j] = 1.f;
        }
#pragma unroll
        for (int j = 0; j < 8; j++) acc_bf(acc, x[j], c[j]);
    }
    for (; i + 4 <= end; i += 4) {
        int s0 = g_esrc[i], s1 = g_esrc[i + 1], s2 = g_esrc[i + 2], s3 = g_esrc[i + 3];
        ull x0 = h[(size_t)s0 * 32 + lane];
        ull x1 = h[(size_t)s1 * 32 + lane];
        ull x2 = h[(size_t)s2 * 32 + lane];
        ull x3 = h[(size_t)s3 * 32 + lane];
        float c0 = 1.f, c1 = 1.f, c2 = 1.f, c3 = 1.f;
        if (MODE) { c0 = g_rscale[i]; c1 = g_rscale[i + 1]; c2 = g_rscale[i + 2]; c3 = g_rscale[i + 3]; }
        acc_bf(acc, x0, c0);
        acc_bf(acc, x1, c1);
        acc_bf(acc, x2, c2);
        acc_bf(acc, x3, c3);
    }
    for (; i < end; i++) {
        ull x = h[(size_t)g_esrc[i] * 32 + lane];
        float c = MODE ? g_rscale[i] : 1.f;
        acc_bf(acc, x, c);
    }

    __nv_bfloat162 o0 = __floats2bfloat162_rn(acc.x, acc.y);
    __nv_bfloat162 o1 = __floats2bfloat162_rn(acc.z, acc.w);
    ull packed = (ull)*reinterpret_cast<unsigned*>(&o0)
               | ((ull)*reinterpret_cast<unsigned*>(&o1) << 32);
    out[(size_t)w * 32 + lane] = packed;
}

// ===========================================================================
// HMMA GEMM, 2-term W split: D = A_bf16 @ (Wt_hi + Wt_lo) + bias (fp32 acc).
// 128x128 tile, 256 threads, 8 warps (4m x 2n), warp tile 32x64, acc=64 regs.
// __launch_bounds__(256, 2): force regs<=128 so 2 CTAs/SM co-reside (the R12
// version without this sat at occ~12% and showed no HMMA gain).
// A32=1: A is fp32 (node_feat), converted to bf16 in registers during staging.
// A32=0: A is bf16, staged via cp.async.
// Uniform 128x32 bf16 tiles, 80B row stride (conflict-free ldmatrix),
// double-buffered, one __syncthreads per chunk. smem 62KB -> 2 CTAs/SM.
// STORE=0 skips C store (last layer).
// ===========================================================================
#define ABUF     10240          // one 128x32 bf16 tile with 80B rows
#define OFF_A    0              // 2 stages
#define OFF_BH   (2 * ABUF)     // 2 stages
#define OFF_BL   (4 * ABUF)     // 2 stages
#define OFF_BIAS (6 * ABUF)
#define GEMM_SMEM (6 * ABUF + 512)   // 61952 bytes

template <int K, int STORE, int A32>
__global__ __launch_bounds__(256, 2)
void gemm_mma(const void* __restrict__ Ap,
              const __nv_bfloat16* __restrict__ WtH,
              const __nv_bfloat16* __restrict__ WtL,
              const float* __restrict__ bias, __nv_bfloat16* __restrict__ C,
              float* __restrict__ colsum_slot, int n, int do_leaky)
{
    constexpr int NCH = K / 32;

    extern __shared__ char smem[];
    const uint32_t sb = smem_u32(smem);
    const int t    = threadIdx.x;
    const int lane = t & 31, wid = t >> 5;
    const int wr   = wid & 3, wc = wid >> 2;
    const int row0 = blockIdx.x * 128;

    if (t < 128) *reinterpret_cast<float*>(smem + OFF_BIAS + t * 4) = bias[t];

    const float*         Af = reinterpret_cast<const float*>(Ap);
    const __nv_bfloat16* Ab = reinterpret_cast<const __nv_bfloat16*>(Ap);

    // cp.async staging geometry: 512 16B slots per tile; thread handles t, t+256
    const int q   = t & 3;
    const int sr0 = t >> 2;
    const int sr1 = 64 + sr0;
    const int ga0 = min(row0 + sr0, n - 1);
    const int ga1 = min(row0 + sr1, n - 1);

    // A32 staging geometry: 1024 float4 slots; thread handles t + j*256
    const int kcol = (t & 7) * 4;       // k offset (4 fp32 -> 4 bf16 = 8B)
    int a32r[4], ga32[4];
#pragma unroll
    for (int j = 0; j < 4; j++) {
        a32r[j]  = (t + j * 256) >> 3;
        ga32[j]  = min(row0 + a32r[j], n - 1);
    }

    auto stageB = [&](int buf, int c) {
        cp16(sb + OFF_BH + buf * ABUF + sr0 * 80 + q * 16,
             WtH + (size_t)sr0 * K + c * 32 + q * 8);
        cp16(sb + OFF_BH + buf * ABUF + sr1 * 80 + q * 16,
             WtH + (size_t)sr1 * K + c * 32 + q * 8);
        cp16(sb + OFF_BL + buf * ABUF + sr0 * 80 + q * 16,
             WtL + (size_t)sr0 * K + c * 32 + q * 8);
        cp16(sb + OFF_BL + buf * ABUF + sr1 * 80 + q * 16,
             WtL + (size_t)sr1 * K + c * 32 + q * 8);
    };
    auto stageA16 = [&](int buf, int c) {
        cp16(sb + OFF_A + buf * ABUF + sr0 * 80 + q * 16,
             Ab + (size_t)ga0 * K + c * 32 + q * 8);
        cp16(sb + OFF_A + buf * ABUF + sr1 * 80 + q * 16,
             Ab + (size_t)ga1 * K + c * 32 + q * 8);
    };

    float4 pv[4];
    auto loadA32 = [&](int c) {
#pragma unroll
        for (int j = 0; j < 4; j++)
            pv[j] = *reinterpret_cast<const float4*>(Af + (size_t)ga32[j] * K + c * 32 + kcol);
    };
    auto storeA32 = [&](int buf) {
#pragma unroll
        for (int j = 0; j < 4; j++) {
            uint2 u = make_uint2(pk_hi(pv[j].x, pv[j].y), pk_hi(pv[j].z, pv[j].w));
            *reinterpret_cast<uint2*>(smem + OFF_A + buf * ABUF + a32r[j] * 80 + kcol * 2) = u;
        }
    };

    float acc[2][8][4];
#pragma unroll
    for (int i = 0; i < 2; i++)
#pragma unroll
        for (int j = 0; j < 8; j++)
#pragma unroll
            for (int p = 0; p < 4; p++) acc[i][j][p] = 0.f;

    // ldmatrix per-lane base addresses (80B row stride)
    const int mat = lane >> 3, lr = lane & 7;
    const uint32_t abase = (uint32_t)((wr * 32 + (mat & 1) * 8 + lr) * 80 + (mat >> 1) * 16);
    const uint32_t bbase = (uint32_t)((wc * 64 + (mat >> 1) * 8 + lr) * 80 + (mat & 1) * 16);

    // ---- prologue: stage chunk 0 ----
    if (A32) { loadA32(0); storeA32(0); }
    else     { stageA16(0, 0); }
    stageB(0, 0);
    cp_commit();

    for (int c = 0; c < NCH; c++) {
        const int cur = c & 1, nxt = cur ^ 1;
        const bool pre = (c + 1 < NCH);
        if (A32 && pre) loadA32(c + 1);     // LDG in flight across the wait
        cp_wait0();
        __syncthreads();                    // chunk cur visible; buffer nxt free
        if (pre) {
            stageB(nxt, c + 1);
            if (!A32) stageA16(nxt, c + 1);
            cp_commit();
            if (A32) storeA32(nxt);
        }

        const uint32_t sA  = sb + OFF_A  + cur * ABUF + abase;
        const uint32_t sBh = sb + OFF_BH + cur * ABUF + bbase;
        const uint32_t sBl = sb + OFF_BL + cur * ABUF + bbase;
#pragma unroll
        for (int ks = 0; ks < 2; ks++) {
            unsigned a0[4], a1[4];
            ldsm4(a0, sA + ks * 32);
            ldsm4(a1, sA + 1280 + ks * 32);   // +16 rows * 80B
#pragma unroll
            for (int np = 0; np < 4; np++) {
                unsigned bh[4], bl[4];
                ldsm4(bh, sBh + np * 1280 + ks * 32);
                ldsm4(bl, sBl + np * 1280 + ks * 32);
                mma16816(acc[0][2 * np],     a0, bh);
                mma16816(acc[0][2 * np + 1], a0, bh + 2);
                mma16816(acc[1][2 * np],     a1, bh);
                mma16816(acc[1][2 * np + 1], a1, bh + 2);
                mma16816(acc[0][2 * np],     a0, bl);
                mma16816(acc[0][2 * np + 1], a0, bl + 2);
                mma16816(acc[1][2 * np],     a1, bl);
                mma16816(acc[1][2 * np + 1], a1, bl + 2);
            }
        }
    }

    // ---- epilogue: bias, leaky, bf16 store, colsum ----
    const float* sbias = reinterpret_cast<const float*>(smem + OFF_BIAS);
    float cs[8][2];
#pragma unroll
    for (int j = 0; j < 8; j++) { cs[j][0] = 0.f; cs[j][1] = 0.f; }

#pragma unroll
    for (int mt = 0; mt < 2; mt++) {
        const int r0 = row0 + wr * 32 + mt * 16 + (lane >> 2);
        const bool ok0 = (r0 < n), ok1 = (r0 + 8 < n);
#pragma unroll
        for (int nt = 0; nt < 8; nt++) {
            const int c0 = wc * 64 + nt * 8 + 2 * (lane & 3);
            float b0 = sbias[c0], b1 = sbias[c0 + 1];
            float v0 = acc[mt][nt][0] + b0;
            float v1 = acc[mt][nt][1] + b1;
            float v2 = acc[mt][nt][2] + b0;
            float v3 = acc[mt][nt][3] + b1;
            if (do_leaky) {
                v0 = v0 > 0.f ? v0 : 0.01f * v0;
                v1 = v1 > 0.f ? v1 : 0.01f * v1;
                v2 = v2 > 0.f ? v2 : 0.01f * v2;
                v3 = v3 > 0.f ? v3 : 0.01f * v3;
            }
            if (!ok0) { v0 = 0.f; v1 = 0.f; }
            if (!ok1) { v2 = 0.f; v3 = 0.f; }
            cs[nt][0] += v0 + v2;
            cs[nt][1] += v1 + v3;
            if (STORE) {
                if (ok0)
                    *reinterpret_cast<__nv_bfloat162*>(C + (size_t)r0 * HD + c0) =
                        __floats2bfloat162_rn(v0, v1);
                if (ok1)
                    *reinterpret_cast<__nv_bfloat162*>(C + (size_t)(r0 + 8) * HD + c0) =
                        __floats2bfloat162_rn(v2, v3);
            }
        }
    }

    // colsum: shfl-reduce over row-groups, then per-wr smem rows (warps wc=0/1
    // write disjoint column halves -> all 4x128 entries valid)
#pragma unroll
    for (int nt = 0; nt < 8; nt++) {
#pragma unroll
        for (int off = 4; off < 32; off <<= 1) {
            cs[nt][0] += __shfl_xor_sync(0xFFFFFFFFu, cs[nt][0], off);
            cs[nt][1] += __shfl_xor_sync(0xFFFFFFFFu, cs[nt][1], off);
        }
    }
    __syncthreads();
    float* sred = reinterpret_cast<float*>(smem + OFF_A);   // reuse A buffers
    if (lane < 4) {
#pragma unroll
        for (int nt = 0; nt < 8; nt++) {
            int c0 = wc * 64 + nt * 8 + 2 * lane;
            sred[wr * 128 + c0]     = cs[nt][0];
            sred[wr * 128 + c0 + 1] = cs[nt][1];
        }
    }
    __syncthreads();
    if (t < 128) {
        float s = 0.f;
#pragma unroll
        for (int r = 0; r < 4; r++) s += sred[r * 128 + t];
        atomicAdd(&colsum_slot[t], s);
    }
}

// ---------------------------------------------------------------------------
// Readout: g = (colsum/N) @ Wpred + bpred ; logits = g @ Wcls + bcls ; softmax
// ---------------------------------------------------------------------------
__global__ void final_kernel(const float* __restrict__ colsum,
                             const float* __restrict__ Wpred, const float* __restrict__ bpred,
                             const float* __restrict__ Wcls,  const float* __restrict__ bcls,
                             float* __restrict__ out, float invn)
{
    __shared__ float g[HD];
    int t = threadIdx.x;
    float acc = bpred[t];
    for (int k = 0; k < (NL + 1) * HD; k++)
        acc = fmaf(colsum[k] * invn, Wpred[k * HD + t], acc);
    g[t] = acc;
    __syncthreads();
    if (t == 0) {
        float l0 = bcls[0], l1 = bcls[1];
        for (int j = 0; j < HD; j++) {
            l0 = fmaf(g[j], Wcls[j * 2 + 0], l0);
            l1 = fmaf(g[j], Wcls[j * 2 + 1], l1);
        }
        float m  = fmaxf(l0, l1);
        float e0 = expf(l0 - m), e1 = expf(l1 - m);
        float inv = 1.0f / (e0 + e1);
        out[0] = e0 * inv;
        out[1] = e1 * inv;
    }
}

// ---------------------------------------------------------------------------
extern "C" void kernel_launch(void* const* d_in, const int* in_sizes, int n_in,
                              void* d_out, int out_size)
{
    const float* node_feat = (const float*)d_in[0];
    const float* degree    = (const float*)d_in[3];
    const float* Wn        = (const float*)d_in[4];
    const float* bn        = (const float*)d_in[5];
    const float* Wgcn      = (const float*)d_in[8];
    const float* bgcn      = (const float*)d_in[9];
    const float* Wpred     = (const float*)d_in[10];
    const float* bpred     = (const float*)d_in[11];
    const float* Wcls      = (const float*)d_in[12];
    const float* bcls      = (const float*)d_in[13];
    const int*   src       = (const int*)d_in[14];
    const int*   dst       = (const int*)d_in[15];

    const int n = in_sizes[3];
    const int e = in_sizes[14];

    float *CS;
    __nv_bfloat16 *AG, *H0, *H1, *WTNH, *WTNL, *WTGH, *WTGL;
    int *CNT;
    cudaGetSymbolAddress((void**)&AG,   g_agg);
    cudaGetSymbolAddress((void**)&H0,   g_h0);
    cudaGetSymbolAddress((void**)&H1,   g_h1);
    cudaGetSymbolAddress((void**)&WTNH, g_wtnh);
    cudaGetSymbolAddress((void**)&WTNL, g_wtnl);
    cudaGetSymbolAddress((void**)&WTGH, g_wtgh);
    cudaGetSymbolAddress((void**)&WTGL, g_wtgl);
    cudaGetSymbolAddress((void**)&CS,   g_colsum);
    cudaGetSymbolAddress((void**)&CNT,  g_cnt);

    static bool init_done = false;
    static cudaStream_t s2;
    static cudaEvent_t ev_fork, ev_join;
    if (!init_done) {
        cudaFuncSetAttribute(gemm_mma<NFK, 1, 1>, cudaFuncAttributeMaxDynamicSharedMemorySize, GEMM_SMEM);
        cudaFuncSetAttribute(gemm_mma<HD, 1, 0>,  cudaFuncAttributeMaxDynamicSharedMemorySize, GEMM_SMEM);
        cudaFuncSetAttribute(gemm_mma<HD, 0, 0>,  cudaFuncAttributeMaxDynamicSharedMemorySize, GEMM_SMEM);
        cudaStreamCreateWithFlags(&s2, cudaStreamNonBlocking);
        cudaEventCreateWithFlags(&ev_fork, cudaEventDisableTiming);
        cudaEventCreateWithFlags(&ev_join, cudaEventDisableTiming);
        init_done = true;
    }

    const int gemm_blocks   = (n + 127) / 128;
    const int edge_blocks   = (e + 255) / 256;
    const int gather_blocks = (n + 7) / 8;

    // ---- fork: CSR build + Wgcn prep on s2, overlapped with input GEMM ----
    cudaEventRecord(ev_fork, 0);
    cudaStreamWaitEvent(s2, ev_fork, 0);

    cudaMemsetAsync(CNT, 0, NN * sizeof(int), s2);
    hist_kernel<<<edge_blocks, 256, 0, s2>>>(dst, e);
    scan_kernel<<<1, 1024, 0, s2>>>(n);
    fill_kernel<<<edge_blocks, 256, 0, s2>>>(src, dst, degree, e);
    prepw_kernel<<<(128 * HD + 255) / 256, 256, 0, s2>>>(Wgcn, WTGH, WTGL, HD);
    cudaEventRecord(ev_join, s2);

    // main stream: Wn prep (small, serial) + gemm256 (A converted in-kernel)
    cudaMemsetAsync(CS, 0, (NL + 1) * HD * sizeof(float));
    prepw_kernel<<<(128 * NFK + 255) / 256, 256>>>(Wn, WTNH, WTNL, NFK);

    // h0 = node_feat @ Wn + bn -> H0 (bf16); colsum slot 0
    gemm_mma<NFK, 1, 1><<<gemm_blocks, 256, GEMM_SMEM>>>(
        node_feat, WTNH, WTNL, bn, H0, CS, n, 0);

    // join: gathers need the CSR; gemm128 needs Wgcn prep
    cudaStreamWaitEvent(0, ev_join, 0);

    // fusion: H1[v] = sum_{u->v} h0[u]
    gather_kernel<0><<<gather_blocks, 256>>>((const ull*)H0, (ull*)H1, n);

    // layer 0: gather H1 -> AG (bf16), gemm AG -> H0
    gather_kernel<1><<<gather_blocks, 256>>>((const ull*)H1, (ull*)AG, n);
    gemm_mma<HD, 1, 0><<<gemm_blocks, 256, GEMM_SMEM>>>(
        AG, WTGH, WTGL, bgcn, H0, CS + 1 * HD, n, 1);

    // layer 1: gather H0 -> AG, gemm AG -> H1
    gather_kernel<1><<<gather_blocks, 256>>>((const ull*)H0, (ull*)AG, n);
    gemm_mma<HD, 1, 0><<<gemm_blocks, 256, GEMM_SMEM>>>(
        AG, WTGH, WTGL, bgcn, H1, CS + 2 * HD, n, 1);

    // layer 2: gather H1 -> AG, gemm colsum-only (h3 never read again)
    gather_kernel<1><<<gather_blocks, 256>>>((const ull*)H1, (ull*)AG, n);
    gemm_mma<HD, 0, 0><<<gemm_blocks, 256, GEMM_SMEM>>>(
        AG, WTGH, WTGL, bgcn, (__nv_bfloat16*)nullptr, CS + 3 * HD, n, 1);

    final_kernel<<<1, HD>>>(CS, Wpred, bpred, Wcls, bcls, (float*)d_out, 1.0f / (float)n);
}